// round 3
// baseline (speedup 1.0000x reference)
#include <cuda_runtime.h>
#include <cuda_bf16.h>
#include <math.h>

#define BATCH 8
#define SEQ   2048
#define EMB   1024
#define HEAD  128
#define NTRI  136            // 16*17/2 lower-triangular 128x128 tiles per batch
#define SCALE 0.03125f       // 1/sqrt(1024)

// ---------------- scratch (__device__ globals: allocation-free) ----------------
__device__ float g_q[BATCH * SEQ * HEAD];
__device__ float g_k[BATCH * SEQ * HEAD];
__device__ float g_v[BATCH * SEQ * HEAD];
__device__ float g_expS[(size_t)BATCH * SEQ * SEQ];   // 128 MB
__device__ float g_colsum[BATCH * SEQ];
__device__ float g_colinv[BATCH * SEQ];

// ---------------- fast exp: FMA-pipe polynomial (scores are small) -------------
__device__ __forceinline__ float fast_exp(float x) {
    float r = 2.0876757e-9f;
    r = fmaf(r, x, 2.5052108e-8f);
    r = fmaf(r, x, 2.7557319e-7f);
    r = fmaf(r, x, 2.7557319e-6f);
    r = fmaf(r, x, 2.4801587e-5f);
    r = fmaf(r, x, 1.9841270e-4f);
    r = fmaf(r, x, 1.3888889e-3f);
    r = fmaf(r, x, 8.3333333e-3f);
    r = fmaf(r, x, 4.1666667e-2f);
    r = fmaf(r, x, 1.6666667e-1f);
    r = fmaf(r, x, 0.5f);
    r = fmaf(r, x, 1.0f);
    r = fmaf(r, x, 1.0f);
    if (fabsf(x) > 2.0f) r = __expf(x);
    return r;
}

__device__ __forceinline__ void tri_decode(int t, int& qt, int& kt) {
    int q = (int)((sqrtf(8.0f * (float)t + 1.0f) - 1.0f) * 0.5f);
    while ((q + 1) * (q + 2) / 2 <= t) q++;
    while (q * (q + 1) / 2 > t) q--;
    qt = q;
    kt = t - q * (q + 1) / 2;
}

// bf16 hi/lo split of an fp32 value
__device__ __forceinline__ void split2(float x, unsigned short& h, unsigned short& l) {
    __nv_bfloat16 bh = __float2bfloat16_rn(x);
    float r = x - __bfloat162float(bh);
    __nv_bfloat16 bl = __float2bfloat16_rn(r);
    h = *(unsigned short*)&bh;
    l = *(unsigned short*)&bl;
}

__device__ __forceinline__ void mma16816(float c[4], const unsigned a[4], const unsigned b[2]) {
    asm volatile(
        "mma.sync.aligned.m16n8k16.row.col.f32.bf16.bf16.f32 "
        "{%0,%1,%2,%3}, {%4,%5,%6,%7}, {%8,%9}, {%0,%1,%2,%3};\n"
        : "+f"(c[0]), "+f"(c[1]), "+f"(c[2]), "+f"(c[3])
        : "r"(a[0]), "r"(a[1]), "r"(a[2]), "r"(a[3]), "r"(b[0]), "r"(b[1]));
}

// ---------------- kernel 0: zero output + column sums --------------------------
__global__ void zero_kernel(float* __restrict__ out) {
    int i = blockIdx.x * blockDim.x + threadIdx.x;
    if (i < BATCH * SEQ * HEAD) out[i] = 0.0f;
    if (i < BATCH * SEQ) g_colsum[i] = 0.0f;
}

// ---------------- kernel 1: QKV projection (tensor cores, bf16 split) ----------
// Y = X @ W via 3x bf16 mma (hi*hi + hi*lo + lo*hi). 128x128 tile, BK=32.
// 8 warps: warp grid 4(M) x 2(N), warp tile 32x64.
__global__ __launch_bounds__(256, 2) void qkv_tc_kernel(
    const float* __restrict__ X, const float* __restrict__ Wq,
    const float* __restrict__ Wk, const float* __restrict__ Wv) {
    const float* W = (blockIdx.z == 0) ? Wq : (blockIdx.z == 1) ? Wk : Wv;
    float* Y       = (blockIdx.z == 0) ? g_q : (blockIdx.z == 1) ? g_k : g_v;

    // padded stride 40 halves -> conflict-free 32-bit fragment loads
    __shared__ unsigned short Ah[128][40], Al[128][40];
    __shared__ unsigned short Bh[128][40], Bl[128][40];   // stored [n][k] (transposed)

    const int tid  = threadIdx.x;
    const int lane = tid & 31;
    const int wid  = tid >> 5;
    const int gid  = lane >> 2, tig = lane & 3;
    const int wm   = wid & 3, wn = wid >> 2;
    const int rowBase = blockIdx.x * 128;

    float c[2][8][4];
#pragma unroll
    for (int m = 0; m < 2; m++)
#pragma unroll
        for (int n = 0; n < 8; n++)
#pragma unroll
            for (int i = 0; i < 4; i++) c[m][n][i] = 0.0f;

    const int arow = tid >> 1;            // 0..127
    const int acol = (tid & 1) * 16;      // 0 / 16

    for (int k0 = 0; k0 < EMB; k0 += 32) {
        // stage loads into registers (no smem dependency yet)
        const float* xp = X + (size_t)(rowBase + arow) * EMB + k0 + acol;
        float4 av[4];
#pragma unroll
        for (int j = 0; j < 4; j++) av[j] = *(const float4*)(xp + j * 4);

        float4 bv[4];
        int bk[4], bn[4];
#pragma unroll
        for (int j = 0; j < 4; j++) {
            int idx = tid + j * 256;              // 0..1023 float4 slots of 32x128 chunk
            bk[j] = idx >> 5;                     // k within chunk 0..31
            bn[j] = (idx & 31) * 4;               // n 0..124
            bv[j] = *(const float4*)(W + (size_t)(k0 + bk[j]) * HEAD + bn[j]);
        }

        __syncthreads();   // previous iteration's fragment reads done

        // A: store split halves [row][k]
#pragma unroll
        for (int j = 0; j < 4; j++) {
            float v[4] = {av[j].x, av[j].y, av[j].z, av[j].w};
#pragma unroll
            for (int i = 0; i < 4; i++) {
                unsigned short h, l;
                split2(v[i], h, l);
                Ah[arow][acol + j * 4 + i] = h;
                Al[arow][acol + j * 4 + i] = l;
            }
        }
        // B: store split halves transposed [n][k]
#pragma unroll
        for (int j = 0; j < 4; j++) {
            float v[4] = {bv[j].x, bv[j].y, bv[j].z, bv[j].w};
#pragma unroll
            for (int i = 0; i < 4; i++) {
                unsigned short h, l;
                split2(v[i], h, l);
                Bh[bn[j] + i][bk[j]] = h;
                Bl[bn[j] + i][bk[j]] = l;
            }
        }
        __syncthreads();

        // two k16 steps
#pragma unroll
        for (int kh = 0; kh < 2; kh++) {
            const int kb = kh * 16 + tig * 2;
            unsigned ah[2][4], al[2][4];
#pragma unroll
            for (int m = 0; m < 2; m++) {
                const int r = wm * 32 + m * 16 + gid;
                ah[m][0] = *(const unsigned*)&Ah[r][kb];
                ah[m][1] = *(const unsigned*)&Ah[r + 8][kb];
                ah[m][2] = *(const unsigned*)&Ah[r][kb + 8];
                ah[m][3] = *(const unsigned*)&Ah[r + 8][kb + 8];
                al[m][0] = *(const unsigned*)&Al[r][kb];
                al[m][1] = *(const unsigned*)&Al[r + 8][kb];
                al[m][2] = *(const unsigned*)&Al[r][kb + 8];
                al[m][3] = *(const unsigned*)&Al[r + 8][kb + 8];
            }
#pragma unroll
            for (int n = 0; n < 8; n++) {
                const int cn = wn * 64 + n * 8 + gid;
                unsigned bh2[2] = {*(const unsigned*)&Bh[cn][kb],
                                   *(const unsigned*)&Bh[cn][kb + 8]};
                unsigned bl2[2] = {*(const unsigned*)&Bl[cn][kb],
                                   *(const unsigned*)&Bl[cn][kb + 8]};
#pragma unroll
                for (int m = 0; m < 2; m++) {
                    mma16816(c[m][n], ah[m], bh2);   // hi*hi
                    mma16816(c[m][n], al[m], bh2);   // lo*hi
                    mma16816(c[m][n], ah[m], bl2);   // hi*lo
                }
            }
        }
    }

    // epilogue
#pragma unroll
    for (int m = 0; m < 2; m++) {
        const int r = rowBase + wm * 32 + m * 16 + gid;
#pragma unroll
        for (int n = 0; n < 8; n++) {
            const int col = wn * 64 + n * 8 + tig * 2;
            *(float2*)(Y + (size_t)r * HEAD + col)       = make_float2(c[m][n][0], c[m][n][1]);
            *(float2*)(Y + (size_t)(r + 8) * HEAD + col) = make_float2(c[m][n][2], c[m][n][3]);
        }
    }
}

// ---------------- kernel 2: scores (lower-tri tiles only, fp32) ----------------
__global__ __launch_bounds__(256, 2) void scores_kernel() {
    const int b = blockIdx.x / NTRI;
    int qt, kt;
    tri_decode(blockIdx.x % NTRI, qt, kt);

    __shared__ float As[8][132];
    __shared__ float Bs[8][132];
    __shared__ float s_col[128];

    const int tid  = threadIdx.x;
    const int tx   = tid & 15, ty = tid >> 4;
    const int lrow = tid >> 1, lc4 = (tid & 1) * 4;

    const float* qp = g_q + ((size_t)b * SEQ + qt * 128 + lrow) * HEAD + lc4;
    const float* kp = g_k + ((size_t)b * SEQ + kt * 128 + lrow) * HEAD + lc4;

    float acc[8][8];
#pragma unroll
    for (int i = 0; i < 8; i++)
#pragma unroll
        for (int j = 0; j < 8; j++) acc[i][j] = 0.0f;

    for (int h0 = 0; h0 < HEAD; h0 += 8) {
        float4 av = *(const float4*)(qp + h0);
        float4 bv = *(const float4*)(kp + h0);
        __syncthreads();
        As[lc4 + 0][lrow] = av.x; As[lc4 + 1][lrow] = av.y;
        As[lc4 + 2][lrow] = av.z; As[lc4 + 3][lrow] = av.w;
        Bs[lc4 + 0][lrow] = bv.x; Bs[lc4 + 1][lrow] = bv.y;
        Bs[lc4 + 2][lrow] = bv.z; Bs[lc4 + 3][lrow] = bv.w;
        __syncthreads();
#pragma unroll
        for (int kk = 0; kk < 8; kk++) {
            float a[8], bb[8];
#pragma unroll
            for (int i = 0; i < 8; i++) a[i] = As[kk][ty * 8 + i];
#pragma unroll
            for (int j = 0; j < 8; j++) bb[j] = Bs[kk][tx * 8 + j];
#pragma unroll
            for (int i = 0; i < 8; i++)
#pragma unroll
                for (int j = 0; j < 8; j++)
                    acc[i][j] = fmaf(a[i], bb[j], acc[i][j]);
        }
    }

    if (tid < 128) s_col[tid] = 0.0f;
    __syncthreads();

    float colpart[8];
#pragma unroll
    for (int j = 0; j < 8; j++) colpart[j] = 0.0f;

    const int r0 = qt * 128 + ty * 8;
    const int c0 = kt * 128 + tx * 8;
#pragma unroll
    for (int i = 0; i < 8; i++) {
        float e[8];
#pragma unroll
        for (int j = 0; j < 8; j++) {
            float s  = acc[i][j] * SCALE;
            float ev = 0.0f;
            if (r0 + i >= c0 + j) ev = fast_exp(s);
            e[j] = ev;
            colpart[j] += ev;
        }
        float* ep = g_expS + ((size_t)b * SEQ + (size_t)(r0 + i)) * SEQ + c0;
        *(float4*)ep       = make_float4(e[0], e[1], e[2], e[3]);
        *(float4*)(ep + 4) = make_float4(e[4], e[5], e[6], e[7]);
    }
#pragma unroll
    for (int j = 0; j < 8; j++) atomicAdd(&s_col[tx * 8 + j], colpart[j]);
    __syncthreads();
    if (tid < 128) atomicAdd(&g_colsum[b * SEQ + kt * 128 + tid], s_col[tid]);
}

// ---------------- kernel 3: reciprocal of column sums --------------------------
__global__ void colinv_kernel() {
    int i = blockIdx.x * blockDim.x + threadIdx.x;
    if (i < BATCH * SEQ) g_colinv[i] = 1.0f / g_colsum[i];
}

// ---------------- kernel 4: out = (expS * colinv) @ v (lower-tri tiles) --------
__global__ __launch_bounds__(256, 2) void out_kernel(float* __restrict__ out) {
    const int b = blockIdx.x / NTRI;
    int qt, kt;
    tri_decode(blockIdx.x % NTRI, qt, kt);

    __shared__ float As[8][132];
    __shared__ float Bs[8][128];
    __shared__ float s_inv[128];

    const int tid = threadIdx.x;
    if (tid < 128) s_inv[tid] = g_colinv[b * SEQ + kt * 128 + tid];

    const int tx   = tid & 15, ty = tid >> 4;
    const int arow = tid >> 1, ac4 = (tid & 1) * 4;
    const int brow = tid >> 5, bc4 = (tid & 31) * 4;

    const float* Ap = g_expS + ((size_t)b * SEQ + qt * 128 + arow) * SEQ + kt * 128 + ac4;
    const float* Vp = g_v + ((size_t)b * SEQ + kt * 128 + brow) * HEAD + bc4;

    float acc[8][8];
#pragma unroll
    for (int i = 0; i < 8; i++)
#pragma unroll
        for (int j = 0; j < 8; j++) acc[i][j] = 0.0f;

    for (int k0 = 0; k0 < 128; k0 += 8) {
        float4 av = *(const float4*)(Ap + k0);
        float4 bv = *(const float4*)(Vp + (size_t)k0 * HEAD);
        __syncthreads();
        As[ac4 + 0][arow] = av.x * s_inv[k0 + ac4 + 0];
        As[ac4 + 1][arow] = av.y * s_inv[k0 + ac4 + 1];
        As[ac4 + 2][arow] = av.z * s_inv[k0 + ac4 + 2];
        As[ac4 + 3][arow] = av.w * s_inv[k0 + ac4 + 3];
        *(float4*)&Bs[brow][bc4] = bv;
        __syncthreads();
#pragma unroll
        for (int kk = 0; kk < 8; kk++) {
            float a[8], bb[8];
#pragma unroll
            for (int i = 0; i < 8; i++) a[i] = As[kk][ty * 8 + i];
#pragma unroll
            for (int j = 0; j < 8; j++) bb[j] = Bs[kk][tx * 8 + j];
#pragma unroll
            for (int i = 0; i < 8; i++)
#pragma unroll
                for (int j = 0; j < 8; j++)
                    acc[i][j] = fmaf(a[i], bb[j], acc[i][j]);
        }
    }
#pragma unroll
    for (int i = 0; i < 8; i++)
#pragma unroll
        for (int j = 0; j < 8; j++)
            atomicAdd(&out[((size_t)b * SEQ + qt * 128 + ty * 8 + i) * HEAD + tx * 8 + j],
                      acc[i][j]);
}

// ---------------- launch --------------------------------------------------------
extern "C" void kernel_launch(void* const* d_in, const int* in_sizes, int n_in,
                              void* d_out, int out_size) {
    const float* X  = (const float*)d_in[0];
    const float* Wq = (const float*)d_in[1];
    const float* Wk = (const float*)d_in[2];
    const float* Wv = (const float*)d_in[3];
    float* out = (float*)d_out;

    zero_kernel<<<(BATCH * SEQ * HEAD + 255) / 256, 256>>>(out);
    qkv_tc_kernel<<<dim3(SEQ * BATCH / 128, 1, 3), 256>>>(X, Wq, Wk, Wv);
    scores_kernel<<<BATCH * NTRI, 256>>>();
    colinv_kernel<<<(BATCH * SEQ + 255) / 256, 256>>>();
    out_kernel<<<BATCH * NTRI, 256>>>(out);
}

// round 6
// speedup vs baseline: 1.1239x; 1.1239x over previous
#include <cuda_runtime.h>
#include <cuda_bf16.h>
#include <math.h>

#define BATCH 8
#define SEQ   2048
#define EMB   1024
#define HEAD  128
#define NTRI  136            // 16*17/2 lower-triangular 128x128 tiles per batch
#define SCALE 0.03125f       // 1/sqrt(1024)

typedef unsigned short ushort_t;

// ---------------- scratch (__device__ globals) — IDENTICAL layout to R2 --------
__device__ float g_q[BATCH * SEQ * HEAD];
__device__ float g_k[BATCH * SEQ * HEAD];
__device__ float g_v[BATCH * SEQ * HEAD];
__device__ float g_expS[(size_t)BATCH * SEQ * SEQ];   // 128 MB
__device__ float g_colsum[BATCH * SEQ];
__device__ float g_colinv[BATCH * SEQ];

// ---------------- helpers ------------------------------------------------------
__device__ __forceinline__ float fast_exp(float x) {
    float r = 2.0876757e-9f;
    r = fmaf(r, x, 2.5052108e-8f);
    r = fmaf(r, x, 2.7557319e-7f);
    r = fmaf(r, x, 2.7557319e-6f);
    r = fmaf(r, x, 2.4801587e-5f);
    r = fmaf(r, x, 1.9841270e-4f);
    r = fmaf(r, x, 1.3888889e-3f);
    r = fmaf(r, x, 8.3333333e-3f);
    r = fmaf(r, x, 4.1666667e-2f);
    r = fmaf(r, x, 1.6666667e-1f);
    r = fmaf(r, x, 0.5f);
    r = fmaf(r, x, 1.0f);
    r = fmaf(r, x, 1.0f);
    if (fabsf(x) > 2.0f) r = __expf(x);
    return r;
}

__device__ __forceinline__ void tri_decode(int t, int& qt, int& kt) {
    int q = (int)((sqrtf(8.0f * (float)t + 1.0f) - 1.0f) * 0.5f);
    while ((q + 1) * (q + 2) / 2 <= t) q++;
    while (q * (q + 1) / 2 > t) q--;
    qt = q;
    kt = t - q * (q + 1) / 2;
}

__device__ __forceinline__ void split2(float x, ushort_t& h, ushort_t& l) {
    __nv_bfloat16 bh = __float2bfloat16_rn(x);
    float r = x - __bfloat162float(bh);
    __nv_bfloat16 bl = __float2bfloat16_rn(r);
    h = *(ushort_t*)&bh;
    l = *(ushort_t*)&bl;
}

__device__ __forceinline__ void mma16816(float c[4], const unsigned a[4], const unsigned b[2]) {
    asm volatile(
        "mma.sync.aligned.m16n8k16.row.col.f32.bf16.bf16.f32 "
        "{%0,%1,%2,%3}, {%4,%5,%6,%7}, {%8,%9}, {%0,%1,%2,%3};\n"
        : "+f"(c[0]), "+f"(c[1]), "+f"(c[2]), "+f"(c[3])
        : "r"(a[0]), "r"(a[1]), "r"(a[2]), "r"(a[3]), "r"(b[0]), "r"(b[1]));
}

// ---------------- kernel 0: zero output + column sums --------------------------
__global__ void zero_kernel(float* __restrict__ out) {
    int i = blockIdx.x * blockDim.x + threadIdx.x;
    if (i < BATCH * SEQ * HEAD) out[i] = 0.0f;
    if (i < BATCH * SEQ) g_colsum[i] = 0.0f;
}

// ---------------- kernel 1: QKV projection (TC, bf16 split) — R2 verbatim ------
__global__ __launch_bounds__(256, 2) void qkv_tc_kernel(
    const float* __restrict__ X, const float* __restrict__ Wq,
    const float* __restrict__ Wk, const float* __restrict__ Wv) {
    const float* W = (blockIdx.z == 0) ? Wq : (blockIdx.z == 1) ? Wk : Wv;
    float* Y       = (blockIdx.z == 0) ? g_q : (blockIdx.z == 1) ? g_k : g_v;

    __shared__ ushort_t Ah[128][40], Al[128][40];
    __shared__ ushort_t Bh[128][40], Bl[128][40];   // [n][k]

    const int tid  = threadIdx.x;
    const int lane = tid & 31;
    const int wid  = tid >> 5;
    const int gid  = lane >> 2, tig = lane & 3;
    const int wm   = wid & 3, wn = wid >> 2;
    const int rowBase = blockIdx.x * 128;

    float c[2][8][4];
#pragma unroll
    for (int m = 0; m < 2; m++)
#pragma unroll
        for (int n = 0; n < 8; n++)
#pragma unroll
            for (int i = 0; i < 4; i++) c[m][n][i] = 0.0f;

    const int arow = tid >> 1;
    const int acol = (tid & 1) * 16;

    for (int k0 = 0; k0 < EMB; k0 += 32) {
        const float* xp = X + (size_t)(rowBase + arow) * EMB + k0 + acol;
        float4 av[4];
#pragma unroll
        for (int j = 0; j < 4; j++) av[j] = *(const float4*)(xp + j * 4);

        float4 bv[4];
        int bk[4], bn[4];
#pragma unroll
        for (int j = 0; j < 4; j++) {
            int idx = tid + j * 256;
            bk[j] = idx >> 5;
            bn[j] = (idx & 31) * 4;
            bv[j] = *(const float4*)(W + (size_t)(k0 + bk[j]) * HEAD + bn[j]);
        }

        __syncthreads();
#pragma unroll
        for (int j = 0; j < 4; j++) {
            float v[4] = {av[j].x, av[j].y, av[j].z, av[j].w};
#pragma unroll
            for (int i = 0; i < 4; i++) {
                ushort_t h, l;
                split2(v[i], h, l);
                Ah[arow][acol + j * 4 + i] = h;
                Al[arow][acol + j * 4 + i] = l;
            }
        }
#pragma unroll
        for (int j = 0; j < 4; j++) {
            float v[4] = {bv[j].x, bv[j].y, bv[j].z, bv[j].w};
#pragma unroll
            for (int i = 0; i < 4; i++) {
                ushort_t h, l;
                split2(v[i], h, l);
                Bh[bn[j] + i][bk[j]] = h;
                Bl[bn[j] + i][bk[j]] = l;
            }
        }
        __syncthreads();

#pragma unroll
        for (int kh = 0; kh < 2; kh++) {
            const int kb = kh * 16 + tig * 2;
            unsigned ah[2][4], al[2][4];
#pragma unroll
            for (int m = 0; m < 2; m++) {
                const int r = wm * 32 + m * 16 + gid;
                ah[m][0] = *(const unsigned*)&Ah[r][kb];
                ah[m][1] = *(const unsigned*)&Ah[r + 8][kb];
                ah[m][2] = *(const unsigned*)&Ah[r][kb + 8];
                ah[m][3] = *(const unsigned*)&Ah[r + 8][kb + 8];
                al[m][0] = *(const unsigned*)&Al[r][kb];
                al[m][1] = *(const unsigned*)&Al[r + 8][kb];
                al[m][2] = *(const unsigned*)&Al[r][kb + 8];
                al[m][3] = *(const unsigned*)&Al[r + 8][kb + 8];
            }
#pragma unroll
            for (int n = 0; n < 8; n++) {
                const int cn = wn * 64 + n * 8 + gid;
                unsigned bh2[2] = {*(const unsigned*)&Bh[cn][kb],
                                   *(const unsigned*)&Bh[cn][kb + 8]};
                unsigned bl2[2] = {*(const unsigned*)&Bl[cn][kb],
                                   *(const unsigned*)&Bl[cn][kb + 8]};
#pragma unroll
                for (int m = 0; m < 2; m++) {
                    mma16816(c[m][n], ah[m], bh2);
                    mma16816(c[m][n], al[m], bh2);
                    mma16816(c[m][n], ah[m], bl2);
                }
            }
        }
    }
#pragma unroll
    for (int m = 0; m < 2; m++) {
        const int r = rowBase + wm * 32 + m * 16 + gid;
#pragma unroll
        for (int n = 0; n < 8; n++) {
            const int col = wn * 64 + n * 8 + tig * 2;
            *(float2*)(Y + (size_t)r * HEAD + col)       = make_float2(c[m][n][0], c[m][n][1]);
            *(float2*)(Y + (size_t)(r + 8) * HEAD + col) = make_float2(c[m][n][2], c[m][n][3]);
        }
    }
}

// ---------------- kernel 2: scores (TC, split-on-stage, lower-tri tiles) -------
// A = q * SCALE (split during staging), B = k (split during staging).
// expS stored fp32; per-key-column sums accumulated.
__global__ __launch_bounds__(256, 2) void scores_tc_kernel() {
    const int b = blockIdx.x / NTRI;
    int qt, kt;
    tri_decode(blockIdx.x % NTRI, qt, kt);

    __shared__ ushort_t Ah[128][40], Al[128][40];
    __shared__ ushort_t Bh[128][40], Bl[128][40];
    __shared__ float s_col[128];

    const int tid  = threadIdx.x;
    const int lane = tid & 31;
    const int wid  = tid >> 5;
    const int gid  = lane >> 2, tig = lane & 3;
    const int wm   = wid & 3, wn = wid >> 2;

    if (tid < 128) s_col[tid] = 0.0f;

    float c[2][8][4];
#pragma unroll
    for (int m = 0; m < 2; m++)
#pragma unroll
        for (int n = 0; n < 8; n++)
#pragma unroll
            for (int i = 0; i < 4; i++) c[m][n][i] = 0.0f;

    const int arow = tid >> 1;
    const int acol = (tid & 1) * 16;
    const float* qp = g_q + (size_t)(b * SEQ + qt * 128 + arow) * HEAD + acol;
    const float* kp = g_k + (size_t)(b * SEQ + kt * 128 + arow) * HEAD + acol;

    for (int k0 = 0; k0 < HEAD; k0 += 32) {
        float4 av[4], bv[4];
#pragma unroll
        for (int j = 0; j < 4; j++) {
            av[j] = *(const float4*)(qp + k0 + j * 4);
            bv[j] = *(const float4*)(kp + k0 + j * 4);
        }
        __syncthreads();
#pragma unroll
        for (int j = 0; j < 4; j++) {
            float va[4] = {av[j].x, av[j].y, av[j].z, av[j].w};
            float vb[4] = {bv[j].x, bv[j].y, bv[j].z, bv[j].w};
#pragma unroll
            for (int i = 0; i < 4; i++) {
                ushort_t h, l;
                split2(va[i] * SCALE, h, l);     // exact power-of-two fold
                Ah[arow][acol + j * 4 + i] = h;
                Al[arow][acol + j * 4 + i] = l;
                split2(vb[i], h, l);
                Bh[arow][acol + j * 4 + i] = h;  // g_k already [n][k]
                Bl[arow][acol + j * 4 + i] = l;
            }
        }
        __syncthreads();

#pragma unroll
        for (int kh = 0; kh < 2; kh++) {
            const int kb = kh * 16 + tig * 2;
            unsigned ah[2][4], al[2][4];
#pragma unroll
            for (int m = 0; m < 2; m++) {
                const int r = wm * 32 + m * 16 + gid;
                ah[m][0] = *(const unsigned*)&Ah[r][kb];
                ah[m][1] = *(const unsigned*)&Ah[r + 8][kb];
                ah[m][2] = *(const unsigned*)&Ah[r][kb + 8];
                ah[m][3] = *(const unsigned*)&Ah[r + 8][kb + 8];
                al[m][0] = *(const unsigned*)&Al[r][kb];
                al[m][1] = *(const unsigned*)&Al[r + 8][kb];
                al[m][2] = *(const unsigned*)&Al[r][kb + 8];
                al[m][3] = *(const unsigned*)&Al[r + 8][kb + 8];
            }
#pragma unroll
            for (int n = 0; n < 8; n++) {
                const int cn = wn * 64 + n * 8 + gid;
                unsigned bh2[2] = {*(const unsigned*)&Bh[cn][kb],
                                   *(const unsigned*)&Bh[cn][kb + 8]};
                unsigned bl2[2] = {*(const unsigned*)&Bl[cn][kb],
                                   *(const unsigned*)&Bl[cn][kb + 8]};
#pragma unroll
                for (int m = 0; m < 2; m++) {
                    mma16816(c[m][n], ah[m], bh2);
                    mma16816(c[m][n], al[m], bh2);
                    mma16816(c[m][n], ah[m], bl2);
                }
            }
        }
    }

    // epilogue: exp + causal mask + fp32 store + column sums
    float p0[8], p1[8];
#pragma unroll
    for (int n = 0; n < 8; n++) { p0[n] = 0.0f; p1[n] = 0.0f; }

#pragma unroll
    for (int m = 0; m < 2; m++) {
        const int r   = wm * 32 + m * 16 + gid;
        const int gq0 = qt * 128 + r;
        const int gq1 = gq0 + 8;
#pragma unroll
        for (int n = 0; n < 8; n++) {
            const int cn = wn * 64 + n * 8 + tig * 2;
            const int gk = kt * 128 + cn;
            float e0 = (gq0 >= gk)     ? fast_exp(c[m][n][0]) : 0.0f;
            float e1 = (gq0 >= gk + 1) ? fast_exp(c[m][n][1]) : 0.0f;
            float e2 = (gq1 >= gk)     ? fast_exp(c[m][n][2]) : 0.0f;
            float e3 = (gq1 >= gk + 1) ? fast_exp(c[m][n][3]) : 0.0f;
            p0[n] += e0 + e2;
            p1[n] += e1 + e3;
            *(float2*)(g_expS + ((size_t)b * SEQ + gq0) * SEQ + gk) = make_float2(e0, e1);
            *(float2*)(g_expS + ((size_t)b * SEQ + gq1) * SEQ + gk) = make_float2(e2, e3);
        }
    }
#pragma unroll
    for (int n = 0; n < 8; n++) {
        p0[n] += __shfl_down_sync(0xffffffff, p0[n], 16);
        p0[n] += __shfl_down_sync(0xffffffff, p0[n], 8);
        p0[n] += __shfl_down_sync(0xffffffff, p0[n], 4);
        p1[n] += __shfl_down_sync(0xffffffff, p1[n], 16);
        p1[n] += __shfl_down_sync(0xffffffff, p1[n], 8);
        p1[n] += __shfl_down_sync(0xffffffff, p1[n], 4);
    }
    if (lane < 4) {   // gid == 0, tig == lane
#pragma unroll
        for (int n = 0; n < 8; n++) {
            atomicAdd(&s_col[wn * 64 + n * 8 + lane * 2],     p0[n]);
            atomicAdd(&s_col[wn * 64 + n * 8 + lane * 2 + 1], p1[n]);
        }
    }
    __syncthreads();
    if (tid < 128) atomicAdd(&g_colsum[b * SEQ + kt * 128 + tid], s_col[tid]);
}

// ---------------- kernel 3: reciprocal of column sums --------------------------
__global__ void colinv_kernel() {
    int i = blockIdx.x * blockDim.x + threadIdx.x;
    if (i < BATCH * SEQ) g_colinv[i] = 1.0f / g_colsum[i];
}

// ---------------- kernel 4: out = (expS*colinv) @ v (TC, split-on-stage) -------
__global__ __launch_bounds__(256, 2) void out_tc_kernel(float* __restrict__ out) {
    const int b = blockIdx.x / NTRI;
    int qt, kt;
    tri_decode(blockIdx.x % NTRI, qt, kt);

    __shared__ ushort_t Ah[128][40], Al[128][40];
    __shared__ ushort_t Bh[128][40], Bl[128][40];   // [head][key]
    __shared__ float s_inv[128];

    const int tid  = threadIdx.x;
    const int lane = tid & 31;
    const int wid  = tid >> 5;
    const int gid  = lane >> 2, tig = lane & 3;
    const int wm   = wid & 3, wn = wid >> 2;

    if (tid < 128) s_inv[tid] = g_colinv[b * SEQ + kt * 128 + tid];

    float c[2][8][4];
#pragma unroll
    for (int m = 0; m < 2; m++)
#pragma unroll
        for (int n = 0; n < 8; n++)
#pragma unroll
            for (int i = 0; i < 4; i++) c[m][n][i] = 0.0f;

    const int arow = tid >> 1;
    const int acol = (tid & 1) * 16;
    const float* ap = g_expS + ((size_t)b * SEQ + qt * 128 + arow) * SEQ + kt * 128 + acol;
    const float* vbase = g_v + (size_t)(b * SEQ + kt * 128) * HEAD;

    for (int k0 = 0; k0 < 128; k0 += 32) {
        float4 av[4];
#pragma unroll
        for (int j = 0; j < 4; j++) av[j] = *(const float4*)(ap + k0 + j * 4);

        float4 bv[4];
        int bk[4], bn[4];
#pragma unroll
        for (int j = 0; j < 4; j++) {
            int idx = tid + j * 256;
            bk[j] = idx >> 5;                 // key within 32-chunk
            bn[j] = (idx & 31) * 4;           // head col
            bv[j] = *(const float4*)(vbase + (size_t)(k0 + bk[j]) * HEAD + bn[j]);
        }

        __syncthreads();
#pragma unroll
        for (int j = 0; j < 4; j++) {
            float va[4] = {av[j].x, av[j].y, av[j].z, av[j].w};
#pragma unroll
            for (int i = 0; i < 4; i++) {
                ushort_t h, l;
                split2(va[i] * s_inv[k0 + acol + j * 4 + i], h, l);
                Ah[arow][acol + j * 4 + i] = h;
                Al[arow][acol + j * 4 + i] = l;
            }
        }
#pragma unroll
        for (int j = 0; j < 4; j++) {
            float v[4] = {bv[j].x, bv[j].y, bv[j].z, bv[j].w};
#pragma unroll
            for (int i = 0; i < 4; i++) {
                ushort_t h, l;
                split2(v[i], h, l);
                Bh[bn[j] + i][bk[j]] = h;
                Bl[bn[j] + i][bk[j]] = l;
            }
        }
        __syncthreads();

#pragma unroll
        for (int kh = 0; kh < 2; kh++) {
            const int kb = kh * 16 + tig * 2;
            unsigned ah[2][4], al[2][4];
#pragma unroll
            for (int m = 0; m < 2; m++) {
                const int r = wm * 32 + m * 16 + gid;
                ah[m][0] = *(const unsigned*)&Ah[r][kb];
                ah[m][1] = *(const unsigned*)&Ah[r + 8][kb];
                ah[m][2] = *(const unsigned*)&Ah[r][kb + 8];
                ah[m][3] = *(const unsigned*)&Ah[r + 8][kb + 8];
                al[m][0] = *(const unsigned*)&Al[r][kb];
                al[m][1] = *(const unsigned*)&Al[r + 8][kb];
                al[m][2] = *(const unsigned*)&Al[r][kb + 8];
                al[m][3] = *(const unsigned*)&Al[r + 8][kb + 8];
            }
#pragma unroll
            for (int n = 0; n < 8; n++) {
                const int cn = wn * 64 + n * 8 + gid;
                unsigned bh2[2] = {*(const unsigned*)&Bh[cn][kb],
                                   *(const unsigned*)&Bh[cn][kb + 8]};
                unsigned bl2[2] = {*(const unsigned*)&Bl[cn][kb],
                                   *(const unsigned*)&Bl[cn][kb + 8]};
#pragma unroll
                for (int m = 0; m < 2; m++) {
                    mma16816(c[m][n], ah[m], bh2);
                    mma16816(c[m][n], al[m], bh2);
                    mma16816(c[m][n], ah[m], bl2);
                }
            }
        }
    }

#pragma unroll
    for (int m = 0; m < 2; m++) {
        const int r = qt * 128 + wm * 32 + m * 16 + gid;
#pragma unroll
        for (int n = 0; n < 8; n++) {
            const int cn = wn * 64 + n * 8 + tig * 2;
            float* op = out + ((size_t)b * SEQ + r) * HEAD + cn;
            atomicAdd(op,     c[m][n][0]);
            atomicAdd(op + 1, c[m][n][1]);
            atomicAdd(op + (size_t)8 * HEAD,     c[m][n][2]);
            atomicAdd(op + (size_t)8 * HEAD + 1, c[m][n][3]);
        }
    }
}

// ---------------- launch --------------------------------------------------------
extern "C" void kernel_launch(void* const* d_in, const int* in_sizes, int n_in,
                              void* d_out, int out_size) {
    const float* X  = (const float*)d_in[0];
    const float* Wq = (const float*)d_in[1];
    const float* Wk = (const float*)d_in[2];
    const float* Wv = (const float*)d_in[3];
    float* out = (float*)d_out;

    zero_kernel<<<(BATCH * SEQ * HEAD + 255) / 256, 256>>>(out);
    qkv_tc_kernel<<<dim3(SEQ * BATCH / 128, 1, 3), 256>>>(X, Wq, Wk, Wv);
    scores_tc_kernel<<<BATCH * NTRI, 256>>>();
    colinv_kernel<<<(BATCH * SEQ + 255) / 256, 256>>>();
    out_tc_kernel<<<BATCH * NTRI, 256>>>(out);
}

// round 8
// speedup vs baseline: 2.2205x; 1.9756x over previous
#include <cuda_runtime.h>
#include <cuda_bf16.h>
#include <math.h>
#include <stdint.h>

#define BATCH 8
#define SEQ   2048
#define EMB   1024
#define HEAD  128
#define NTRI  136            // lower-tri 128x128 tiles per batch
#define SCALE 0.03125f       // 1/sqrt(1024)

typedef unsigned short ushort_t;

// ---------------- global scratch: pre-split bf16 hi/lo arrays -------------------
__device__ ushort_t g_xh[BATCH * SEQ * EMB], g_xl[BATCH * SEQ * EMB];     // X split [row][emb]
__device__ ushort_t g_wth[3 * HEAD * EMB],   g_wtl[3 * HEAD * EMB];       // W^T split [mat][head][emb]
__device__ ushort_t g_qh[BATCH * SEQ * HEAD], g_ql[BATCH * SEQ * HEAD];   // q' split [tok][head]
__device__ ushort_t g_kh[BATCH * SEQ * HEAD], g_kl[BATCH * SEQ * HEAD];   // k  split [tok][head]
__device__ ushort_t g_vth[BATCH * HEAD * SEQ], g_vtl[BATCH * HEAD * SEQ]; // (v*inv)^T split [head][key]
__device__ ushort_t g_eh[(size_t)BATCH * SEQ * SEQ];                      // expS hi [q][key] 64MB
__device__ ushort_t g_el[(size_t)BATCH * SEQ * SEQ];                      // expS lo 64MB
__device__ float    g_v[BATCH * SEQ * HEAD];
__device__ float    g_colsum[BATCH * SEQ], g_colinv[BATCH * SEQ];

// ---------------- helpers ------------------------------------------------------
__device__ __forceinline__ uint32_t smem_u32(const void* p) {
    uint32_t a;
    asm("{ .reg .u64 t; cvta.to.shared.u64 t, %1; cvt.u32.u64 %0, t; }" : "=r"(a) : "l"(p));
    return a;
}
__device__ __forceinline__ float fast_exp(float x) {
    float r = 2.0876757e-9f;
    r = fmaf(r, x, 2.5052108e-8f);
    r = fmaf(r, x, 2.7557319e-7f);
    r = fmaf(r, x, 2.7557319e-6f);
    r = fmaf(r, x, 2.4801587e-5f);
    r = fmaf(r, x, 1.9841270e-4f);
    r = fmaf(r, x, 1.3888889e-3f);
    r = fmaf(r, x, 8.3333333e-3f);
    r = fmaf(r, x, 4.1666667e-2f);
    r = fmaf(r, x, 1.6666667e-1f);
    r = fmaf(r, x, 0.5f);
    r = fmaf(r, x, 1.0f);
    r = fmaf(r, x, 1.0f);
    if (fabsf(x) > 2.0f) r = __expf(x);
    return r;
}
__device__ __forceinline__ void tri_decode(int t, int& qt, int& kt) {
    int q = (int)((sqrtf(8.0f * (float)t + 1.0f) - 1.0f) * 0.5f);
    while ((q + 1) * (q + 2) / 2 <= t) q++;
    while (q * (q + 1) / 2 > t) q--;
    qt = q;
    kt = t - q * (q + 1) / 2;
}
__device__ __forceinline__ void split2(float x, ushort_t& h, ushort_t& l) {
    __nv_bfloat16 bh = __float2bfloat16_rn(x);
    float r = x - __bfloat162float(bh);
    __nv_bfloat16 bl = __float2bfloat16_rn(r);
    h = *(ushort_t*)&bh;
    l = *(ushort_t*)&bl;
}
__device__ __forceinline__ void splitpack(float x0, float x1, unsigned& hh, unsigned& ll) {
    ushort_t h0, l0, h1, l1;
    split2(x0, h0, l0);
    split2(x1, h1, l1);
    hh = (unsigned)h0 | ((unsigned)h1 << 16);
    ll = (unsigned)l0 | ((unsigned)l1 << 16);
}
__device__ __forceinline__ void mma16816(float c[4], const unsigned a[4], const unsigned b[2]) {
    asm volatile(
        "mma.sync.aligned.m16n8k16.row.col.f32.bf16.bf16.f32 "
        "{%0,%1,%2,%3}, {%4,%5,%6,%7}, {%8,%9}, {%0,%1,%2,%3};\n"
        : "+f"(c[0]), "+f"(c[1]), "+f"(c[2]), "+f"(c[3])
        : "r"(a[0]), "r"(a[1]), "r"(a[2]), "r"(a[3]), "r"(b[0]), "r"(b[1]));
}
__device__ __forceinline__ void ldsm_x4(unsigned* r, uint32_t a) {
    asm volatile("ldmatrix.sync.aligned.m8n8.x4.shared.b16 {%0,%1,%2,%3}, [%4];"
                 : "=r"(r[0]), "=r"(r[1]), "=r"(r[2]), "=r"(r[3]) : "r"(a));
}

// Shared GEMM inner: A,B staged in smem slabs [128][40] ushort (hi at base, lo at +10240B).
// Computes c += A(128x32chunk) * B^T for this warp's 32x64 tile, both k16 halves.
__device__ __forceinline__ void chunk_mma(uint32_t aHi, uint32_t bHi, int lane, int wm, int wn,
                                          float c[2][8][4]) {
    const uint32_t aAddr = aHi + (uint32_t)(wm * 32 + (lane & 15)) * 80u + ((lane >> 4) * 8u) * 2u;
    const uint32_t bAddr = bHi + (uint32_t)(wn * 64 + (lane & 7) + (((lane >> 4) & 1) * 8)) * 80u
                         + (((lane >> 3) & 1) * 8u) * 2u;
#pragma unroll
    for (int kh = 0; kh < 2; kh++) {
        const uint32_t ko = kh * 32u;
        unsigned ah[2][4], al[2][4];
        ldsm_x4(ah[0], aAddr + ko);
        ldsm_x4(ah[1], aAddr + 1280u + ko);
        ldsm_x4(al[0], aAddr + 10240u + ko);
        ldsm_x4(al[1], aAddr + 11520u + ko);
#pragma unroll
        for (int j = 0; j < 4; j++) {
            unsigned bh4[4], bl4[4];
            ldsm_x4(bh4, bAddr + (uint32_t)j * 1280u + ko);
            ldsm_x4(bl4, bAddr + (uint32_t)j * 1280u + 10240u + ko);
#pragma unroll
            for (int nn = 0; nn < 2; nn++) {
                const int n = j * 2 + nn;
                unsigned bh2[2] = {bh4[nn * 2], bh4[nn * 2 + 1]};
                unsigned bl2[2] = {bl4[nn * 2], bl4[nn * 2 + 1]};
#pragma unroll
                for (int m = 0; m < 2; m++) {
                    mma16816(c[m][n], ah[m], bh2);
                    mma16816(c[m][n], al[m], bh2);
                    mma16816(c[m][n], ah[m], bl2);
                }
            }
        }
    }
}

// ---------------- kernel 0: zero -----------------------------------------------
__global__ void zero_kernel(float* __restrict__ out) {
    int i = blockIdx.x * blockDim.x + threadIdx.x;
    if (i < BATCH * SEQ * HEAD) out[i] = 0.0f;
    if (i < BATCH * SEQ) g_colsum[i] = 0.0f;
}

// ---------------- prep: split X ------------------------------------------------
__global__ __launch_bounds__(256) void prep_x(const float* __restrict__ X) {
    int p = blockIdx.x * 256 + threadIdx.x;      // pair index over 16384*512
    int row = p >> 9, kp = (p & 511) * 2;
    float2 v = *(const float2*)(X + (size_t)row * EMB + kp);
    unsigned hh, ll;
    splitpack(v.x, v.y, hh, ll);
    *(unsigned*)&g_xh[(size_t)row * EMB + kp] = hh;
    *(unsigned*)&g_xl[(size_t)row * EMB + kp] = ll;
}

// ---------------- prep: split W^T ----------------------------------------------
__global__ __launch_bounds__(256) void prep_w(const float* __restrict__ Wq,
                                              const float* __restrict__ Wk,
                                              const float* __restrict__ Wv) {
    int p = blockIdx.x * 256 + threadIdx.x;      // over 3*128*512
    int mat = p >> 16;
    int rem = p & 65535;
    int n = rem >> 9, kp = (rem & 511) * 2;
    const float* W = (mat == 0) ? Wq : (mat == 1) ? Wk : Wv;
    float v0 = W[(size_t)kp * HEAD + n];
    float v1 = W[(size_t)(kp + 1) * HEAD + n];
    unsigned hh, ll;
    splitpack(v0, v1, hh, ll);
    size_t off = (size_t)(mat * HEAD + n) * EMB + kp;
    *(unsigned*)&g_wth[off] = hh;
    *(unsigned*)&g_wtl[off] = ll;
}

// ---------------- kernel 1: QKV (ldmatrix + mma.sync, pre-split) ---------------
__global__ __launch_bounds__(256) void qkv_tc(void) {
    __shared__ ushort_t S[4][128][40];           // Ah, Al, Bh, Bl
    const int tid = threadIdx.x, lane = tid & 31, wid = tid >> 5;
    const int wm = wid & 3, wn = wid >> 2;
    const int rt = blockIdx.x, mat = blockIdx.y;
    const uint32_t sb = smem_u32(S);

    float c[2][8][4];
#pragma unroll
    for (int m = 0; m < 2; m++)
#pragma unroll
        for (int n = 0; n < 8; n++)
#pragma unroll
            for (int i = 0; i < 4; i++) c[m][n][i] = 0.0f;

    const int r0 = tid >> 2, seg = (tid & 3) * 8;
    const ushort_t* Ah = g_xh + (size_t)(rt * 128) * EMB;
    const ushort_t* Al = g_xl + (size_t)(rt * 128) * EMB;
    const ushort_t* Bh = g_wth + (size_t)(mat * HEAD) * EMB;
    const ushort_t* Bl = g_wtl + (size_t)(mat * HEAD) * EMB;

    for (int kc = 0; kc < 32; kc++) {
        const int k0 = kc * 32;
        uint4 tA0 = *(const uint4*)&Ah[(size_t)r0 * EMB + k0 + seg];
        uint4 tA1 = *(const uint4*)&Ah[(size_t)(r0 + 64) * EMB + k0 + seg];
        uint4 tL0 = *(const uint4*)&Al[(size_t)r0 * EMB + k0 + seg];
        uint4 tL1 = *(const uint4*)&Al[(size_t)(r0 + 64) * EMB + k0 + seg];
        uint4 tB0 = *(const uint4*)&Bh[(size_t)r0 * EMB + k0 + seg];
        uint4 tB1 = *(const uint4*)&Bh[(size_t)(r0 + 64) * EMB + k0 + seg];
        uint4 tM0 = *(const uint4*)&Bl[(size_t)r0 * EMB + k0 + seg];
        uint4 tM1 = *(const uint4*)&Bl[(size_t)(r0 + 64) * EMB + k0 + seg];
        __syncthreads();
        *(uint4*)&S[0][r0][seg]      = tA0;
        *(uint4*)&S[0][r0 + 64][seg] = tA1;
        *(uint4*)&S[1][r0][seg]      = tL0;
        *(uint4*)&S[1][r0 + 64][seg] = tL1;
        *(uint4*)&S[2][r0][seg]      = tB0;
        *(uint4*)&S[2][r0 + 64][seg] = tB1;
        *(uint4*)&S[3][r0][seg]      = tM0;
        *(uint4*)&S[3][r0 + 64][seg] = tM1;
        __syncthreads();
        chunk_mma(sb, sb + 20480u, lane, wm, wn, c);
    }

    const int gid = lane >> 2, tig = lane & 3;
    if (mat == 2) {
#pragma unroll
        for (int m = 0; m < 2; m++) {
            const int r = rt * 128 + wm * 32 + m * 16 + gid;
#pragma unroll
            for (int n = 0; n < 8; n++) {
                const int col = wn * 64 + n * 8 + tig * 2;
                *(float2*)(g_v + (size_t)r * HEAD + col)       = make_float2(c[m][n][0], c[m][n][1]);
                *(float2*)(g_v + (size_t)(r + 8) * HEAD + col) = make_float2(c[m][n][2], c[m][n][3]);
            }
        }
    } else {
        ushort_t* Yh = (mat == 0) ? g_qh : g_kh;
        ushort_t* Yl = (mat == 0) ? g_ql : g_kl;
        const float sc = (mat == 0) ? SCALE : 1.0f;
#pragma unroll
        for (int m = 0; m < 2; m++) {
            const int r = rt * 128 + wm * 32 + m * 16 + gid;
#pragma unroll
            for (int n = 0; n < 8; n++) {
                const int col = wn * 64 + n * 8 + tig * 2;
                unsigned hh, ll;
                splitpack(c[m][n][0] * sc, c[m][n][1] * sc, hh, ll);
                *(unsigned*)&Yh[(size_t)r * HEAD + col] = hh;
                *(unsigned*)&Yl[(size_t)r * HEAD + col] = ll;
                splitpack(c[m][n][2] * sc, c[m][n][3] * sc, hh, ll);
                *(unsigned*)&Yh[(size_t)(r + 8) * HEAD + col] = hh;
                *(unsigned*)&Yl[(size_t)(r + 8) * HEAD + col] = ll;
            }
        }
    }
}

// ---------------- kernel 2: scores ---------------------------------------------
__global__ __launch_bounds__(256) void scores_tc(void) {
    __shared__ ushort_t S[4][128][40];
    __shared__ float s_col[128];
    const int tid = threadIdx.x, lane = tid & 31, wid = tid >> 5;
    const int wm = wid & 3, wn = wid >> 2;
    const int b = blockIdx.x / NTRI;
    int qt, kt;
    tri_decode(blockIdx.x % NTRI, qt, kt);
    const uint32_t sb = smem_u32(S);

    if (tid < 128) s_col[tid] = 0.0f;

    float c[2][8][4];
#pragma unroll
    for (int m = 0; m < 2; m++)
#pragma unroll
        for (int n = 0; n < 8; n++)
#pragma unroll
            for (int i = 0; i < 4; i++) c[m][n][i] = 0.0f;

    const int r0 = tid >> 2, seg = (tid & 3) * 8;
    const ushort_t* Ah = g_qh + (size_t)(b * SEQ + qt * 128) * HEAD;
    const ushort_t* Al = g_ql + (size_t)(b * SEQ + qt * 128) * HEAD;
    const ushort_t* Bh = g_kh + (size_t)(b * SEQ + kt * 128) * HEAD;
    const ushort_t* Bl = g_kl + (size_t)(b * SEQ + kt * 128) * HEAD;

    for (int kc = 0; kc < 4; kc++) {
        const int k0 = kc * 32;
        uint4 tA0 = *(const uint4*)&Ah[(size_t)r0 * HEAD + k0 + seg];
        uint4 tA1 = *(const uint4*)&Ah[(size_t)(r0 + 64) * HEAD + k0 + seg];
        uint4 tL0 = *(const uint4*)&Al[(size_t)r0 * HEAD + k0 + seg];
        uint4 tL1 = *(const uint4*)&Al[(size_t)(r0 + 64) * HEAD + k0 + seg];
        uint4 tB0 = *(const uint4*)&Bh[(size_t)r0 * HEAD + k0 + seg];
        uint4 tB1 = *(const uint4*)&Bh[(size_t)(r0 + 64) * HEAD + k0 + seg];
        uint4 tM0 = *(const uint4*)&Bl[(size_t)r0 * HEAD + k0 + seg];
        uint4 tM1 = *(const uint4*)&Bl[(size_t)(r0 + 64) * HEAD + k0 + seg];
        __syncthreads();
        *(uint4*)&S[0][r0][seg]      = tA0;
        *(uint4*)&S[0][r0 + 64][seg] = tA1;
        *(uint4*)&S[1][r0][seg]      = tL0;
        *(uint4*)&S[1][r0 + 64][seg] = tL1;
        *(uint4*)&S[2][r0][seg]      = tB0;
        *(uint4*)&S[2][r0 + 64][seg] = tB1;
        *(uint4*)&S[3][r0][seg]      = tM0;
        *(uint4*)&S[3][r0 + 64][seg] = tM1;
        __syncthreads();
        chunk_mma(sb, sb + 20480u, lane, wm, wn, c);
    }

    const int gid = lane >> 2, tig = lane & 3;
    float p0[8], p1[8];
#pragma unroll
    for (int n = 0; n < 8; n++) { p0[n] = 0.0f; p1[n] = 0.0f; }

#pragma unroll
    for (int m = 0; m < 2; m++) {
        const int r   = wm * 32 + m * 16 + gid;
        const int gq0 = qt * 128 + r;
        const int gq1 = gq0 + 8;
#pragma unroll
        for (int n = 0; n < 8; n++) {
            const int cn = wn * 64 + n * 8 + tig * 2;
            const int gk = kt * 128 + cn;
            float e0 = (gq0 >= gk)     ? fast_exp(c[m][n][0]) : 0.0f;
            float e1 = (gq0 >= gk + 1) ? fast_exp(c[m][n][1]) : 0.0f;
            float e2 = (gq1 >= gk)     ? fast_exp(c[m][n][2]) : 0.0f;
            float e3 = (gq1 >= gk + 1) ? fast_exp(c[m][n][3]) : 0.0f;
            p0[n] += e0 + e2;
            p1[n] += e1 + e3;
            unsigned hh, ll;
            size_t base0 = ((size_t)b * SEQ + gq0) * SEQ + gk;
            splitpack(e0, e1, hh, ll);
            *(unsigned*)&g_eh[base0] = hh;
            *(unsigned*)&g_el[base0] = ll;
            size_t base1 = ((size_t)b * SEQ + gq1) * SEQ + gk;
            splitpack(e2, e3, hh, ll);
            *(unsigned*)&g_eh[base1] = hh;
            *(unsigned*)&g_el[base1] = ll;
        }
    }
#pragma unroll
    for (int n = 0; n < 8; n++) {
        p0[n] += __shfl_down_sync(0xffffffff, p0[n], 16);
        p0[n] += __shfl_down_sync(0xffffffff, p0[n], 8);
        p0[n] += __shfl_down_sync(0xffffffff, p0[n], 4);
        p1[n] += __shfl_down_sync(0xffffffff, p1[n], 16);
        p1[n] += __shfl_down_sync(0xffffffff, p1[n], 8);
        p1[n] += __shfl_down_sync(0xffffffff, p1[n], 4);
    }
    if (lane < 4) {
#pragma unroll
        for (int n = 0; n < 8; n++) {
            atomicAdd(&s_col[wn * 64 + n * 8 + lane * 2],     p0[n]);
            atomicAdd(&s_col[wn * 64 + n * 8 + lane * 2 + 1], p1[n]);
        }
    }
    __syncthreads();
    if (tid < 128) atomicAdd(&g_colsum[b * SEQ + kt * 128 + tid], s_col[tid]);
}

// ---------------- kernel 3: colinv ---------------------------------------------
__global__ void colinv_kernel() {
    int i = blockIdx.x * blockDim.x + threadIdx.x;
    if (i < BATCH * SEQ) g_colinv[i] = 1.0f / g_colsum[i];
}

// ---------------- kernel 4: vprep — (v*inv)^T split ----------------------------
__global__ __launch_bounds__(256) void vprep_kernel() {
    __shared__ ushort_t sh[128][72], sl[128][72];
    const int tid   = threadIdx.x;
    const int batch = blockIdx.x >> 5;
    const int kt64  = blockIdx.x & 31;

    const int r  = tid >> 2;            // key row 0..63
    const int cb = (tid & 3) * 32;      // head col base
    const int key = batch * SEQ + kt64 * 64 + r;
    const float inv = 1.0f / g_colsum[key];
    const float* vp = g_v + (size_t)key * HEAD + cb;
#pragma unroll
    for (int j = 0; j < 8; j++) {
        float4 v4 = *(const float4*)(vp + j * 4);
        float v[4] = {v4.x, v4.y, v4.z, v4.w};
#pragma unroll
        for (int i = 0; i < 4; i++) {
            ushort_t h, l;
            split2(v[i] * inv, h, l);
            sh[cb + j * 4 + i][r] = h;
            sl[cb + j * 4 + i][r] = l;
        }
    }
    __syncthreads();
    const int h  = tid >> 1;
    const int kc = (tid & 1) * 32;
    size_t gbase = (size_t)(batch * HEAD + h) * SEQ + kt64 * 64 + kc;
#pragma unroll
    for (int j = 0; j < 4; j++) {
        uint2 u0 = *(const uint2*)&sh[h][kc + j * 8];
        uint2 u1 = *(const uint2*)&sh[h][kc + j * 8 + 4];
        *(uint4*)&g_vth[gbase + j * 8] = make_uint4(u0.x, u0.y, u1.x, u1.y);
        uint2 w0 = *(const uint2*)&sl[h][kc + j * 8];
        uint2 w1 = *(const uint2*)&sl[h][kc + j * 8 + 4];
        *(uint4*)&g_vtl[gbase + j * 8] = make_uint4(w0.x, w0.y, w1.x, w1.y);
    }
}

// ---------------- kernel 5: out = expS' @ v' -----------------------------------
__global__ __launch_bounds__(256) void out_tc(float* __restrict__ out) {
    __shared__ ushort_t S[4][128][40];
    const int tid = threadIdx.x, lane = tid & 31, wid = tid >> 5;
    const int wm = wid & 3, wn = wid >> 2;
    const int b = blockIdx.x / NTRI;
    int qt, kt;
    tri_decode(blockIdx.x % NTRI, qt, kt);
    const uint32_t sb = smem_u32(S);

    float c[2][8][4];
#pragma unroll
    for (int m = 0; m < 2; m++)
#pragma unroll
        for (int n = 0; n < 8; n++)
#pragma unroll
            for (int i = 0; i < 4; i++) c[m][n][i] = 0.0f;

    const int r0 = tid >> 2, seg = (tid & 3) * 8;
    const ushort_t* Ah = g_eh + ((size_t)b * SEQ + qt * 128) * SEQ + kt * 128;
    const ushort_t* Al = g_el + ((size_t)b * SEQ + qt * 128) * SEQ + kt * 128;
    const ushort_t* Bh = g_vth + (size_t)(b * HEAD) * SEQ + kt * 128;
    const ushort_t* Bl = g_vtl + (size_t)(b * HEAD) * SEQ + kt * 128;

    for (int kc = 0; kc < 4; kc++) {
        const int k0 = kc * 32;
        uint4 tA0 = *(const uint4*)&Ah[(size_t)r0 * SEQ + k0 + seg];
        uint4 tA1 = *(const uint4*)&Ah[(size_t)(r0 + 64) * SEQ + k0 + seg];
        uint4 tL0 = *(const uint4*)&Al[(size_t)r0 * SEQ + k0 + seg];
        uint4 tL1 = *(const uint4*)&Al[(size_t)(r0 + 64) * SEQ + k0 + seg];
        uint4 tB0 = *(const uint4*)&Bh[(size_t)r0 * SEQ + k0 + seg];
        uint4 tB1 = *(const uint4*)&Bh[(size_t)(r0 + 64) * SEQ + k0 + seg];
        uint4 tM0 = *(const uint4*)&Bl[(size_t)r0 * SEQ + k0 + seg];
        uint4 tM1 = *(const uint4*)&Bl[(size_t)(r0 + 64) * SEQ + k0 + seg];
        __syncthreads();
        *(uint4*)&S[0][r0][seg]      = tA0;
        *(uint4*)&S[0][r0 + 64][seg] = tA1;
        *(uint4*)&S[1][r0][seg]      = tL0;
        *(uint4*)&S[1][r0 + 64][seg] = tL1;
        *(uint4*)&S[2][r0][seg]      = tB0;
        *(uint4*)&S[2][r0 + 64][seg] = tB1;
        *(uint4*)&S[3][r0][seg]      = tM0;
        *(uint4*)&S[3][r0 + 64][seg] = tM1;
        __syncthreads();
        chunk_mma(sb, sb + 20480u, lane, wm, wn, c);
    }

    const int gid = lane >> 2, tig = lane & 3;
#pragma unroll
    for (int m = 0; m < 2; m++) {
        const int r = qt * 128 + wm * 32 + m * 16 + gid;
#pragma unroll
        for (int n = 0; n < 8; n++) {
            const int cn = wn * 64 + n * 8 + tig * 2;
            float* op = out + ((size_t)b * SEQ + r) * HEAD + cn;
            atomicAdd(op,     c[m][n][0]);
            atomicAdd(op + 1, c[m][n][1]);
            atomicAdd(op + (size_t)8 * HEAD,     c[m][n][2]);
            atomicAdd(op + (size_t)8 * HEAD + 1, c[m][n][3]);
        }
    }
}

// ---------------- launch --------------------------------------------------------
extern "C" void kernel_launch(void* const* d_in, const int* in_sizes, int n_in,
                              void* d_out, int out_size) {
    const float* X  = (const float*)d_in[0];
    const float* Wq = (const float*)d_in[1];
    const float* Wk = (const float*)d_in[2];
    const float* Wv = (const float*)d_in[3];
    float* out = (float*)d_out;

    zero_kernel<<<(BATCH * SEQ * HEAD + 255) / 256, 256>>>(out);
    prep_x<<<BATCH * SEQ * EMB / 2 / 256, 256>>>(X);
    prep_w<<<3 * HEAD * EMB / 2 / 256, 256>>>(Wq, Wk, Wv);
    qkv_tc<<<dim3(BATCH * SEQ / 128, 3), 256>>>();
    scores_tc<<<BATCH * NTRI, 256>>>();
    colinv_kernel<<<(BATCH * SEQ + 255) / 256, 256>>>();
    vprep_kernel<<<BATCH * SEQ / 64, 256>>>();
    out_tc<<<BATCH * NTRI, 256>>>(out);
}

// round 9
// speedup vs baseline: 2.3635x; 1.0644x over previous
#include <cuda_runtime.h>
#include <cuda_bf16.h>
#include <math.h>
#include <stdint.h>

#define BATCH 8
#define SEQ   2048
#define EMB   1024
#define HEAD  128
#define NTRI  136            // lower-tri 128x128 tiles per batch
#define SCALE 0.03125f       // 1/sqrt(1024)

typedef unsigned short ushort_t;

// Stage geometry: 4 slabs of [128][40] ushort = 10240B each; stage = 40960B.
#define SLAB  10240u
#define STAGE 40960u

// ---------------- global scratch: pre-split bf16 hi/lo arrays -------------------
__device__ ushort_t g_xh[BATCH * SEQ * EMB], g_xl[BATCH * SEQ * EMB];     // X split [row][emb]
__device__ ushort_t g_wth[3 * HEAD * EMB],   g_wtl[3 * HEAD * EMB];       // W^T split [mat][head][emb]
__device__ ushort_t g_qh[BATCH * SEQ * HEAD], g_ql[BATCH * SEQ * HEAD];   // q' split [tok][head]
__device__ ushort_t g_kh[BATCH * SEQ * HEAD], g_kl[BATCH * SEQ * HEAD];   // k  split [tok][head]
__device__ ushort_t g_vth[BATCH * HEAD * SEQ], g_vtl[BATCH * HEAD * SEQ]; // (v*inv)^T split [head][key]
__device__ ushort_t g_eh[(size_t)BATCH * SEQ * SEQ];                      // expS hi [q][key] 64MB
__device__ ushort_t g_el[(size_t)BATCH * SEQ * SEQ];                      // expS lo 64MB
__device__ float    g_v[BATCH * SEQ * HEAD];
__device__ float    g_colsum[BATCH * SEQ];

// ---------------- helpers ------------------------------------------------------
__device__ __forceinline__ uint32_t smem_u32(const void* p) {
    uint32_t a;
    asm("{ .reg .u64 t; cvta.to.shared.u64 t, %1; cvt.u32.u64 %0, t; }" : "=r"(a) : "l"(p));
    return a;
}
__device__ __forceinline__ void cpa16(uint32_t dst, const void* src) {
    asm volatile("cp.async.cg.shared.global [%0], [%1], 16;" :: "r"(dst), "l"(src));
}
__device__ __forceinline__ float fast_exp(float x) {
    float r = 2.0876757e-9f;
    r = fmaf(r, x, 2.5052108e-8f);
    r = fmaf(r, x, 2.7557319e-7f);
    r = fmaf(r, x, 2.7557319e-6f);
    r = fmaf(r, x, 2.4801587e-5f);
    r = fmaf(r, x, 1.9841270e-4f);
    r = fmaf(r, x, 1.3888889e-3f);
    r = fmaf(r, x, 8.3333333e-3f);
    r = fmaf(r, x, 4.1666667e-2f);
    r = fmaf(r, x, 1.6666667e-1f);
    r = fmaf(r, x, 0.5f);
    r = fmaf(r, x, 1.0f);
    r = fmaf(r, x, 1.0f);
    if (fabsf(x) > 2.0f) r = __expf(x);
    return r;
}
__device__ __forceinline__ void tri_decode(int t, int& qt, int& kt) {
    int q = (int)((sqrtf(8.0f * (float)t + 1.0f) - 1.0f) * 0.5f);
    while ((q + 1) * (q + 2) / 2 <= t) q++;
    while (q * (q + 1) / 2 > t) q--;
    qt = q;
    kt = t - q * (q + 1) / 2;
}
__device__ __forceinline__ void split2(float x, ushort_t& h, ushort_t& l) {
    __nv_bfloat16 bh = __float2bfloat16_rn(x);
    float r = x - __bfloat162float(bh);
    __nv_bfloat16 bl = __float2bfloat16_rn(r);
    h = *(ushort_t*)&bh;
    l = *(ushort_t*)&bl;
}
__device__ __forceinline__ void splitpack(float x0, float x1, unsigned& hh, unsigned& ll) {
    ushort_t h0, l0, h1, l1;
    split2(x0, h0, l0);
    split2(x1, h1, l1);
    hh = (unsigned)h0 | ((unsigned)h1 << 16);
    ll = (unsigned)l0 | ((unsigned)l1 << 16);
}
__device__ __forceinline__ void mma16816(float c[4], const unsigned a[4], const unsigned b[2]) {
    asm volatile(
        "mma.sync.aligned.m16n8k16.row.col.f32.bf16.bf16.f32 "
        "{%0,%1,%2,%3}, {%4,%5,%6,%7}, {%8,%9}, {%0,%1,%2,%3};\n"
        : "+f"(c[0]), "+f"(c[1]), "+f"(c[2]), "+f"(c[3])
        : "r"(a[0]), "r"(a[1]), "r"(a[2]), "r"(a[3]), "r"(b[0]), "r"(b[1]));
}
__device__ __forceinline__ void ldsm_x4(unsigned* r, uint32_t a) {
    asm volatile("ldmatrix.sync.aligned.m8n8.x4.shared.b16 {%0,%1,%2,%3}, [%4];"
                 : "=r"(r[0]), "=r"(r[1]), "=r"(r[2]), "=r"(r[3]) : "r"(a));
}

// Issue one stage's cp.async loads: 4 slabs (Ah, Al, Bh, Bl), 2 rows x 16B per thread per slab.
__device__ __forceinline__ void stage_issue(
    uint32_t base, const ushort_t* Ah, const ushort_t* Al,
    const ushort_t* Bh, const ushort_t* Bl,
    size_t strideA, size_t strideB, int k0, int r0, int seg) {
    const uint32_t ro = (uint32_t)r0 * 80u + (uint32_t)seg * 2u;
    cpa16(base + ro,                  Ah + (size_t)r0 * strideA + k0 + seg);
    cpa16(base + ro + 5120u,          Ah + (size_t)(r0 + 64) * strideA + k0 + seg);
    cpa16(base + SLAB + ro,           Al + (size_t)r0 * strideA + k0 + seg);
    cpa16(base + SLAB + ro + 5120u,   Al + (size_t)(r0 + 64) * strideA + k0 + seg);
    cpa16(base + 2*SLAB + ro,         Bh + (size_t)r0 * strideB + k0 + seg);
    cpa16(base + 2*SLAB + ro + 5120u, Bh + (size_t)(r0 + 64) * strideB + k0 + seg);
    cpa16(base + 3*SLAB + ro,         Bl + (size_t)r0 * strideB + k0 + seg);
    cpa16(base + 3*SLAB + ro + 5120u, Bl + (size_t)(r0 + 64) * strideB + k0 + seg);
    asm volatile("cp.async.commit_group;");
}

// GEMM inner on one staged chunk: warp computes its 32x64 tile over k=32.
__device__ __forceinline__ void chunk_mma(uint32_t aHi, uint32_t bHi, int lane, int wm, int wn,
                                          float c[2][8][4]) {
    const uint32_t aAddr = aHi + (uint32_t)(wm * 32 + (lane & 15)) * 80u + ((lane >> 4) * 8u) * 2u;
    const uint32_t bAddr = bHi + (uint32_t)(wn * 64 + (lane & 7) + (((lane >> 4) & 1) * 8)) * 80u
                         + (((lane >> 3) & 1) * 8u) * 2u;
#pragma unroll
    for (int kh = 0; kh < 2; kh++) {
        const uint32_t ko = kh * 32u;
        unsigned ah[2][4], al[2][4];
        ldsm_x4(ah[0], aAddr + ko);
        ldsm_x4(ah[1], aAddr + 1280u + ko);
        ldsm_x4(al[0], aAddr + SLAB + ko);
        ldsm_x4(al[1], aAddr + SLAB + 1280u + ko);
#pragma unroll
        for (int j = 0; j < 4; j++) {
            unsigned bh4[4], bl4[4];
            ldsm_x4(bh4, bAddr + (uint32_t)j * 1280u + ko);
            ldsm_x4(bl4, bAddr + (uint32_t)j * 1280u + SLAB + ko);
#pragma unroll
            for (int nn = 0; nn < 2; nn++) {
                const int n = j * 2 + nn;
                unsigned bh2[2] = {bh4[nn * 2], bh4[nn * 2 + 1]};
                unsigned bl2[2] = {bl4[nn * 2], bl4[nn * 2 + 1]};
#pragma unroll
                for (int m = 0; m < 2; m++) {
                    mma16816(c[m][n], ah[m], bh2);
                    mma16816(c[m][n], al[m], bh2);
                    mma16816(c[m][n], ah[m], bl2);
                }
            }
        }
    }
}

// Pipelined tile GEMM over NC chunks of k=32. Two stages of dynamic smem.
__device__ __forceinline__ void tile_gemm(
    uint32_t sb, const ushort_t* Ah, const ushort_t* Al,
    const ushort_t* Bh, const ushort_t* Bl,
    size_t strideA, size_t strideB, int NC, int tid, float c[2][8][4]) {
    const int lane = tid & 31, wid = tid >> 5;
    const int wm = wid & 3, wn = wid >> 2;
    const int r0 = tid >> 2, seg = (tid & 3) * 8;

    stage_issue(sb, Ah, Al, Bh, Bl, strideA, strideB, 0, r0, seg);
    for (int kc = 0; kc < NC; kc++) {
        const int s = kc & 1;
        if (kc + 1 < NC) {
            stage_issue(sb + (uint32_t)(s ^ 1) * STAGE, Ah, Al, Bh, Bl,
                        strideA, strideB, (kc + 1) * 32, r0, seg);
            asm volatile("cp.async.wait_group 1;");
        } else {
            asm volatile("cp.async.wait_group 0;");
        }
        __syncthreads();
        const uint32_t base = sb + (uint32_t)s * STAGE;
        chunk_mma(base, base + 2*SLAB, lane, wm, wn, c);
        __syncthreads();
    }
}

// ---------------- kernel 0: zero -----------------------------------------------
__global__ void zero_kernel(float* __restrict__ out) {
    int i = blockIdx.x * blockDim.x + threadIdx.x;
    if (i < BATCH * SEQ * HEAD) out[i] = 0.0f;
    if (i < BATCH * SEQ) g_colsum[i] = 0.0f;
}

// ---------------- prep: split X ------------------------------------------------
__global__ __launch_bounds__(256) void prep_x(const float* __restrict__ X) {
    int p = blockIdx.x * 256 + threadIdx.x;
    int row = p >> 9, kp = (p & 511) * 2;
    float2 v = *(const float2*)(X + (size_t)row * EMB + kp);
    unsigned hh, ll;
    splitpack(v.x, v.y, hh, ll);
    *(unsigned*)&g_xh[(size_t)row * EMB + kp] = hh;
    *(unsigned*)&g_xl[(size_t)row * EMB + kp] = ll;
}

// ---------------- prep: split W^T ----------------------------------------------
__global__ __launch_bounds__(256) void prep_w(const float* __restrict__ Wq,
                                              const float* __restrict__ Wk,
                                              const float* __restrict__ Wv) {
    int p = blockIdx.x * 256 + threadIdx.x;
    int mat = p >> 16;
    int rem = p & 65535;
    int n = rem >> 9, kp = (rem & 511) * 2;
    const float* W = (mat == 0) ? Wq : (mat == 1) ? Wk : Wv;
    float v0 = W[(size_t)kp * HEAD + n];
    float v1 = W[(size_t)(kp + 1) * HEAD + n];
    unsigned hh, ll;
    splitpack(v0, v1, hh, ll);
    size_t off = (size_t)(mat * HEAD + n) * EMB + kp;
    *(unsigned*)&g_wth[off] = hh;
    *(unsigned*)&g_wtl[off] = ll;
}

// ---------------- kernel 1: QKV ------------------------------------------------
__global__ __launch_bounds__(256, 2) void qkv_tc(void) {
    extern __shared__ ushort_t dynS[];
    const int tid = threadIdx.x, lane = tid & 31, wid = tid >> 5;
    const int wm = wid & 3, wn = wid >> 2;
    const int rt = blockIdx.x, mat = blockIdx.y;
    const uint32_t sb = smem_u32(dynS);

    float c[2][8][4];
#pragma unroll
    for (int m = 0; m < 2; m++)
#pragma unroll
        for (int n = 0; n < 8; n++)
#pragma unroll
            for (int i = 0; i < 4; i++) c[m][n][i] = 0.0f;

    tile_gemm(sb,
              g_xh + (size_t)(rt * 128) * EMB, g_xl + (size_t)(rt * 128) * EMB,
              g_wth + (size_t)(mat * HEAD) * EMB, g_wtl + (size_t)(mat * HEAD) * EMB,
              EMB, EMB, 32, tid, c);

    const int gid = lane >> 2, tig = lane & 3;
    if (mat == 2) {
#pragma unroll
        for (int m = 0; m < 2; m++) {
            const int r = rt * 128 + wm * 32 + m * 16 + gid;
#pragma unroll
            for (int n = 0; n < 8; n++) {
                const int col = wn * 64 + n * 8 + tig * 2;
                *(float2*)(g_v + (size_t)r * HEAD + col)       = make_float2(c[m][n][0], c[m][n][1]);
                *(float2*)(g_v + (size_t)(r + 8) * HEAD + col) = make_float2(c[m][n][2], c[m][n][3]);
            }
        }
    } else {
        ushort_t* Yh = (mat == 0) ? g_qh : g_kh;
        ushort_t* Yl = (mat == 0) ? g_ql : g_kl;
        const float sc = (mat == 0) ? SCALE : 1.0f;
#pragma unroll
        for (int m = 0; m < 2; m++) {
            const int r = rt * 128 + wm * 32 + m * 16 + gid;
#pragma unroll
            for (int n = 0; n < 8; n++) {
                const int col = wn * 64 + n * 8 + tig * 2;
                unsigned hh, ll;
                splitpack(c[m][n][0] * sc, c[m][n][1] * sc, hh, ll);
                *(unsigned*)&Yh[(size_t)r * HEAD + col] = hh;
                *(unsigned*)&Yl[(size_t)r * HEAD + col] = ll;
                splitpack(c[m][n][2] * sc, c[m][n][3] * sc, hh, ll);
                *(unsigned*)&Yh[(size_t)(r + 8) * HEAD + col] = hh;
                *(unsigned*)&Yl[(size_t)(r + 8) * HEAD + col] = ll;
            }
        }
    }
}

// ---------------- kernel 2: scores ---------------------------------------------
__global__ __launch_bounds__(256, 2) void scores_tc(void) {
    extern __shared__ ushort_t dynS[];
    __shared__ float s_col[128];
    const int tid = threadIdx.x, lane = tid & 31, wid = tid >> 5;
    const int wm = wid & 3, wn = wid >> 2;
    const int b = blockIdx.x / NTRI;
    int qt, kt;
    tri_decode(blockIdx.x % NTRI, qt, kt);
    const uint32_t sb = smem_u32(dynS);

    if (tid < 128) s_col[tid] = 0.0f;

    float c[2][8][4];
#pragma unroll
    for (int m = 0; m < 2; m++)
#pragma unroll
        for (int n = 0; n < 8; n++)
#pragma unroll
            for (int i = 0; i < 4; i++) c[m][n][i] = 0.0f;

    tile_gemm(sb,
              g_qh + (size_t)(b * SEQ + qt * 128) * HEAD, g_ql + (size_t)(b * SEQ + qt * 128) * HEAD,
              g_kh + (size_t)(b * SEQ + kt * 128) * HEAD, g_kl + (size_t)(b * SEQ + kt * 128) * HEAD,
              HEAD, HEAD, 4, tid, c);

    const int gid = lane >> 2, tig = lane & 3;
    float p0[8], p1[8];
#pragma unroll
    for (int n = 0; n < 8; n++) { p0[n] = 0.0f; p1[n] = 0.0f; }

#pragma unroll
    for (int m = 0; m < 2; m++) {
        const int r   = wm * 32 + m * 16 + gid;
        const int gq0 = qt * 128 + r;
        const int gq1 = gq0 + 8;
#pragma unroll
        for (int n = 0; n < 8; n++) {
            const int cn = wn * 64 + n * 8 + tig * 2;
            const int gk = kt * 128 + cn;
            float e0 = (gq0 >= gk)     ? fast_exp(c[m][n][0]) : 0.0f;
            float e1 = (gq0 >= gk + 1) ? fast_exp(c[m][n][1]) : 0.0f;
            float e2 = (gq1 >= gk)     ? fast_exp(c[m][n][2]) : 0.0f;
            float e3 = (gq1 >= gk + 1) ? fast_exp(c[m][n][3]) : 0.0f;
            p0[n] += e0 + e2;
            p1[n] += e1 + e3;
            unsigned hh, ll;
            size_t base0 = ((size_t)b * SEQ + gq0) * SEQ + gk;
            splitpack(e0, e1, hh, ll);
            *(unsigned*)&g_eh[base0] = hh;
            *(unsigned*)&g_el[base0] = ll;
            size_t base1 = ((size_t)b * SEQ + gq1) * SEQ + gk;
            splitpack(e2, e3, hh, ll);
            *(unsigned*)&g_eh[base1] = hh;
            *(unsigned*)&g_el[base1] = ll;
        }
    }
#pragma unroll
    for (int n = 0; n < 8; n++) {
        p0[n] += __shfl_down_sync(0xffffffff, p0[n], 16);
        p0[n] += __shfl_down_sync(0xffffffff, p0[n], 8);
        p0[n] += __shfl_down_sync(0xffffffff, p0[n], 4);
        p1[n] += __shfl_down_sync(0xffffffff, p1[n], 16);
        p1[n] += __shfl_down_sync(0xffffffff, p1[n], 8);
        p1[n] += __shfl_down_sync(0xffffffff, p1[n], 4);
    }
    if (lane < 4) {
#pragma unroll
        for (int n = 0; n < 8; n++) {
            atomicAdd(&s_col[wn * 64 + n * 8 + lane * 2],     p0[n]);
            atomicAdd(&s_col[wn * 64 + n * 8 + lane * 2 + 1], p1[n]);
        }
    }
    __syncthreads();
    if (tid < 128) atomicAdd(&g_colsum[b * SEQ + kt * 128 + tid], s_col[tid]);
}

// ---------------- kernel 3: vprep — (v*inv)^T split ----------------------------
__global__ __launch_bounds__(256) void vprep_kernel() {
    __shared__ ushort_t sh[128][72], sl[128][72];
    const int tid   = threadIdx.x;
    const int batch = blockIdx.x >> 5;
    const int kt64  = blockIdx.x & 31;

    const int r  = tid >> 2;
    const int cb = (tid & 3) * 32;
    const int key = batch * SEQ + kt64 * 64 + r;
    const float inv = 1.0f / g_colsum[key];
    const float* vp = g_v + (size_t)key * HEAD + cb;
#pragma unroll
    for (int j = 0; j < 8; j++) {
        float4 v4 = *(const float4*)(vp + j * 4);
        float v[4] = {v4.x, v4.y, v4.z, v4.w};
#pragma unroll
        for (int i = 0; i < 4; i++) {
            ushort_t h, l;
            split2(v[i] * inv, h, l);
            sh[cb + j * 4 + i][r] = h;
            sl[cb + j * 4 + i][r] = l;
        }
    }
    __syncthreads();
    const int h  = tid >> 1;
    const int kc = (tid & 1) * 32;
    size_t gbase = (size_t)(batch * HEAD + h) * SEQ + kt64 * 64 + kc;
#pragma unroll
    for (int j = 0; j < 4; j++) {
        uint2 u0 = *(const uint2*)&sh[h][kc + j * 8];
        uint2 u1 = *(const uint2*)&sh[h][kc + j * 8 + 4];
        *(uint4*)&g_vth[gbase + j * 8] = make_uint4(u0.x, u0.y, u1.x, u1.y);
        uint2 w0 = *(const uint2*)&sl[h][kc + j * 8];
        uint2 w1 = *(const uint2*)&sl[h][kc + j * 8 + 4];
        *(uint4*)&g_vtl[gbase + j * 8] = make_uint4(w0.x, w0.y, w1.x, w1.y);
    }
}

// ---------------- kernel 4: out = expS' @ v' -----------------------------------
__global__ __launch_bounds__(256, 2) void out_tc(float* __restrict__ out) {
    extern __shared__ ushort_t dynS[];
    const int tid = threadIdx.x, lane = tid & 31, wid = tid >> 5;
    const int wm = wid & 3, wn = wid >> 2;
    const int b = blockIdx.x / NTRI;
    int qt, kt;
    tri_decode(blockIdx.x % NTRI, qt, kt);
    const uint32_t sb = smem_u32(dynS);

    float c[2][8][4];
#pragma unroll
    for (int m = 0; m < 2; m++)
#pragma unroll
        for (int n = 0; n < 8; n++)
#pragma unroll
            for (int i = 0; i < 4; i++) c[m][n][i] = 0.0f;

    tile_gemm(sb,
              g_eh + ((size_t)b * SEQ + qt * 128) * SEQ + kt * 128,
              g_el + ((size_t)b * SEQ + qt * 128) * SEQ + kt * 128,
              g_vth + (size_t)(b * HEAD) * SEQ + kt * 128,
              g_vtl + (size_t)(b * HEAD) * SEQ + kt * 128,
              SEQ, SEQ, 4, tid, c);

    const int gid = lane >> 2, tig = lane & 3;
#pragma unroll
    for (int m = 0; m < 2; m++) {
        const int r = qt * 128 + wm * 32 + m * 16 + gid;
#pragma unroll
        for (int n = 0; n < 8; n++) {
            const int cn = wn * 64 + n * 8 + tig * 2;
            float* op = out + ((size_t)b * SEQ + r) * HEAD + cn;
            atomicAdd(op,     c[m][n][0]);
            atomicAdd(op + 1, c[m][n][1]);
            atomicAdd(op + (size_t)8 * HEAD,     c[m][n][2]);
            atomicAdd(op + (size_t)8 * HEAD + 1, c[m][n][3]);
        }
    }
}

// ---------------- launch --------------------------------------------------------
extern "C" void kernel_launch(void* const* d_in, const int* in_sizes, int n_in,
                              void* d_out, int out_size) {
    const float* X  = (const float*)d_in[0];
    const float* Wq = (const float*)d_in[1];
    const float* Wk = (const float*)d_in[2];
    const float* Wv = (const float*)d_in[3];
    float* out = (float*)d_out;

    const int smem = 2 * 40960;
    cudaFuncSetAttribute(qkv_tc,    cudaFuncAttributeMaxDynamicSharedMemorySize, smem);
    cudaFuncSetAttribute(scores_tc, cudaFuncAttributeMaxDynamicSharedMemorySize, smem);
    cudaFuncSetAttribute(out_tc,    cudaFuncAttributeMaxDynamicSharedMemorySize, smem);

    zero_kernel<<<(BATCH * SEQ * HEAD + 255) / 256, 256>>>(out);
    prep_x<<<BATCH * SEQ * EMB / 2 / 256, 256>>>(X);
    prep_w<<<3 * HEAD * EMB / 2 / 256, 256>>>(Wq, Wk, Wv);
    qkv_tc<<<dim3(BATCH * SEQ / 128, 3), 256, smem>>>();
    scores_tc<<<BATCH * NTRI, 256, smem>>>();
    vprep_kernel<<<BATCH * SEQ / 64, 256>>>();
    out_tc<<<BATCH * NTRI, 256, smem>>>(out);
}